// round 17
// baseline (speedup 1.0000x reference)
#include <cuda_runtime.h>
#include <cstdint>

// ============================================================================
// Layer_70411693850653 — equivariant GNN layer. (R16 + degree-sorted tiles)
//
//  * messages[384:640] never consumed -> skipped
//  * agg == 1.5 * feats[:, :128] -> skip connection folded into weights
//  * scatter_mean via bucketed inverse-CSR + register gather (no float atomics)
//  * Phase B = tf32 mma.sync.m16n8k8, paired-column LDS.64 fragments (R16)
//  * R17: nodes counting-sorted by degree (33 bins, 3 tiny kernels) so each
//    8-node tile has ~equal degrees -> Phase A barrier pays mean, not max
//  * Phase A: depth-2 pipelined edge loop (MLP=2)
//  * NO cross-barrier prefetch (twice-measured regression)
// ============================================================================

#define N_MAX 50000
#define CAP   32
#define TILE  8
#define FSP   104        // stride words: 52%16==4 -> LDS.64 conflict-free
#define NBLK  740        // 5 per SM on 148 SMs
#define BINS  33
#define PBMAX ((N_MAX + 255) / 256)

__device__ int  g_deg[N_MAX];            // zero-init at load; k_main resets
__device__ int2 g_bucket[N_MAX * CAP];   // {sender, edge}
__device__ int  g_bcnt [PBMAX * BINS];   // per-block bin counts
__device__ int  g_bbase[PBMAX * BINS];   // per-block bin bases
__device__ int2 g_order[N_MAX];          // degree-sorted {node, deg}

// ---------------------------------------------------------------------------
__global__ void k_fill(const int* __restrict__ recv,
                       const int* __restrict__ senders, int E) {
    int e = blockIdx.x * blockDim.x + threadIdx.x;
    if (e < E) {
        int r = recv[e];
        int slot = atomicAdd(&g_deg[r], 1);
        if (slot < CAP) g_bucket[r * CAP + slot] = make_int2(senders[e], e);
    }
}

// ---------------------------------------------------------------------------
__global__ void k_count(int N) {
    __shared__ int scnt[BINS];
    int t = threadIdx.x, b = blockIdx.x;
    if (t < BINS) scnt[t] = 0;
    __syncthreads();
    int n = b * 256 + t;
    if (n < N) atomicAdd(&scnt[min(g_deg[n], 32)], 1);
    __syncthreads();
    if (t < BINS) g_bcnt[b * BINS + t] = scnt[t];
}

__global__ void k_scan(int nb) {
    __shared__ int tot[BINS];
    __shared__ int binstart[BINS];
    int t = threadIdx.x;
    if (t < BINS) {
        int s = 0;
        for (int b = 0; b < nb; b++) s += g_bcnt[b * BINS + t];
        tot[t] = s;
    }
    __syncthreads();
    if (t == 0) {
        int acc = 0;
        for (int d = 0; d < BINS; d++) { binstart[d] = acc; acc += tot[d]; }
    }
    __syncthreads();
    if (t < BINS) {
        int acc = binstart[t];
        for (int b = 0; b < nb; b++) {
            g_bbase[b * BINS + t] = acc;
            acc += g_bcnt[b * BINS + t];
        }
    }
}

__global__ void k_place(int N) {
    __shared__ int scnt[BINS];
    int t = threadIdx.x, b = blockIdx.x;
    if (t < BINS) scnt[t] = 0;
    __syncthreads();
    int n = b * 256 + t;
    if (n < N) {
        int dg = g_deg[n];
        int d  = min(dg, 32);
        int r  = atomicAdd(&scnt[d], 1);
        g_order[g_bbase[b * BINS + d] + r] = make_int2(n, dg);
    }
}

// ---------------------------------------------------------------------------
__device__ __forceinline__ uint32_t f2tf(float x) {
    uint32_t r;
    asm("cvt.rna.tf32.f32 %0, %1;" : "=r"(r) : "f"(x));
    return r;
}

__device__ __forceinline__ void mma_tf32(float c[4],
    uint32_t a0, uint32_t a1, uint32_t a2, uint32_t a3,
    uint32_t b0, uint32_t b1)
{
    asm volatile(
        "mma.sync.aligned.m16n8k8.row.col.f32.tf32.tf32.f32 "
        "{%0,%1,%2,%3}, {%4,%5,%6,%7}, {%8,%9}, {%0,%1,%2,%3};"
        : "+f"(c[0]), "+f"(c[1]), "+f"(c[2]), "+f"(c[3])
        : "r"(a0), "r"(a1), "r"(a2), "r"(a3), "r"(b0), "r"(b1));
}

__device__ __forceinline__ int pcol(int c) {
    return (c & ~7) + 2 * (c & 3) + ((c >> 2) & 1);
}

// ---------------------------------------------------------------------------
// sF rows: 0-7 scalar | 8-15 x | 16-23 y | 24-31 z | 32-39 shared zero pad
__global__ void __launch_bounds__(256, 5) k_main(
    const float* __restrict__ nf, const float* __restrict__ sh,
    const float* __restrict__ W0, const float* __restrict__ W1,
    const float* __restrict__ Ws0, const float* __restrict__ Ws1,
    float* __restrict__ out, int N)
{
    __shared__ uint32_t sF [40 * FSP];       // tf32 feats rows   (16.6 KB)
    __shared__ uint32_t sW0[32 * FSP];       // Wt0[v][u] tf32    (13.3 KB)
    __shared__ uint32_t sW1[32 * FSP];       // Wt1[v][u] tf32    (13.3 KB)
    __shared__ int      sNode[TILE];         // tile's original node ids

    const float invA = 0.10206207261596575f;         // 1/sqrt(96)
    const float cB   = 1.5f * 0.17677669529663687f;  // 1.5/sqrt(32)
    const float INV_SQRT3 = 0.5773502691896258f;

    const int t    = threadIdx.x;
    const int w    = t >> 5;
    const int lane = t & 31;

    // ---- prologue: effective weights, transposed [v][u], permuted cols ----
    for (int i = t; i < 96 * 32; i += 256) {
        int u = i >> 5, v = i & 31;
        float w0 = W0[i] * invA;
        float w1 = W1[i] * invA;
        if (u < 32) { w0 = fmaf(cB, Ws0[i], w0); w1 = fmaf(cB, Ws1[i], w1); }
        int pc = pcol(u);
        sW0[v * FSP + pc] = f2tf(w0);
        sW1[v * FSP + pc] = f2tf(w1);
    }
    for (int i = t; i < 8 * FSP; i += 256)
        sF[32 * FSP + i] = 0;

    // fragment indices (loop-invariant)
    const int r0 = lane >> 2;   // 0..7
    const int c0 = lane & 3;    // 0..3
    const int plane = (lane & 24) + 2 * (lane & 3) + ((lane >> 2) & 1);
    const int m  = w >> 1;                  // 0=scalar, 1=x|y, 2=z
    const int nh = w & 1;
    const int nbase = nh * 16;
    const uint32_t* Wt = (m == 0) ? sW0 : sW1;
    const int loR = ((m == 0) ? 0 : (m == 1) ? 8 : 24) + r0;
    const int hiR = ((m == 1) ? 16 : 32) + r0;      // pad rows for m=0,2

    const int ntiles = (N + TILE - 1) / TILE;
    for (int tile = blockIdx.x; tile < ntiles; tile += gridDim.x) {
        __syncthreads();   // previous tile's Phase B readers done with sF/sNode

        // ---------------- Phase A: warp w owns sorted slot tile*8 + w ------
        {
            const int idx = tile * TILE + w;
            int node = -1, d = 0;
            if (idx < N) {
                int2 od = g_order[idx];
                node = od.x;
                d    = od.y;
            }
            if (lane == 0) sNode[w] = node;
            const int dc = min(d, CAP);
            if (node >= 0 && lane == 0) g_deg[node] = 0;  // zero-invariant

            float a0 = 0.f, ax = 0.f, ay = 0.f, az = 0.f;
            float p00 = 0.f, dot = 0.f;
            float qx = 0.f, qy = 0.f, qz = 0.f;   // p01 = s0*f1
            float rx = 0.f, ry = 0.f, rz = 0.f;   // p10 = f0*s1

            int    my_s  = 0;
            float4 my_sh = make_float4(0.f, 0.f, 0.f, 0.f);
            if (node >= 0 && lane < dc) {
                int2 se = g_bucket[node * CAP + lane];
                my_s    = se.x;
                my_sh   = *reinterpret_cast<const float4*>(sh + (size_t)se.y * 4);
            }

            if (dc > 0) {
                // ---- depth-2 pipelined edge loop (MLP=2) ----
                int s0i = __shfl_sync(0xffffffffu, my_s, 0);
                const float* row0 = nf + (size_t)s0i * 128;
                float f0 = row0[lane];
                float g0 = row0[32 + 3 * lane];
                float g1 = row0[33 + 3 * lane];
                float g2 = row0[34 + 3 * lane];

                for (int j = 0; j < dc; j++) {
                    float nf0 = 0.f, ng0 = 0.f, ng1 = 0.f, ng2 = 0.f;
                    if (j + 1 < dc) {
                        int sn = __shfl_sync(0xffffffffu, my_s, j + 1);
                        const float* rn = nf + (size_t)sn * 128;
                        nf0 = rn[lane];
                        ng0 = rn[32 + 3 * lane];
                        ng1 = rn[33 + 3 * lane];
                        ng2 = rn[34 + 3 * lane];
                    }
                    float s0  = __shfl_sync(0xffffffffu, my_sh.x, j);
                    float s1x = __shfl_sync(0xffffffffu, my_sh.y, j);
                    float s1y = __shfl_sync(0xffffffffu, my_sh.z, j);
                    float s1z = __shfl_sync(0xffffffffu, my_sh.w, j);

                    a0 += f0; ax += g0; ay += g1; az += g2;
                    p00 = fmaf(s0, f0, p00);
                    dot = fmaf(s1x, g0, fmaf(s1y, g1, fmaf(s1z, g2, dot)));
                    qx  = fmaf(s0, g0, qx);
                    qy  = fmaf(s0, g1, qy);
                    qz  = fmaf(s0, g2, qz);
                    rx  = fmaf(f0, s1x, rx);
                    ry  = fmaf(f0, s1y, ry);
                    rz  = fmaf(f0, s1z, rz);

                    f0 = nf0; g0 = ng0; g1 = ng1; g2 = ng2;
                }
            }

            const float scale = 1.0f / (1.5f * (float)max(d, 1));
            sF[ w       * FSP +      plane] = f2tf(a0 * scale);
            sF[ w       * FSP + 32 + plane] = f2tf(p00 * scale);
            sF[ w       * FSP + 64 + plane] = f2tf(dot * scale * INV_SQRT3);
            sF[( 8 + w) * FSP +      plane] = f2tf(ax * scale);
            sF[( 8 + w) * FSP + 32 + plane] = f2tf(qx * scale);
            sF[( 8 + w) * FSP + 64 + plane] = f2tf(rx * scale);
            sF[(16 + w) * FSP +      plane] = f2tf(ay * scale);
            sF[(16 + w) * FSP + 32 + plane] = f2tf(qy * scale);
            sF[(16 + w) * FSP + 64 + plane] = f2tf(ry * scale);
            sF[(24 + w) * FSP +      plane] = f2tf(az * scale);
            sF[(24 + w) * FSP + 32 + plane] = f2tf(qz * scale);
            sF[(24 + w) * FSP + 64 + plane] = f2tf(rz * scale);
        }
        __syncthreads();   // sF + sNode ready

        // ---------------- Phase B: tf32 MMA, warps 0..5, LDS.64 frags ------
        if (w < 6) {
            float c[2][4];
            #pragma unroll
            for (int nt = 0; nt < 2; nt++)
                #pragma unroll
                for (int i = 0; i < 4; i++) c[nt][i] = 0.f;

            #pragma unroll
            for (int k = 0; k < 12; k++) {
                const int kb = 8 * k + 2 * c0;
                uint2 alo = *reinterpret_cast<const uint2*>(&sF[loR * FSP + kb]);
                uint2 ahi = *reinterpret_cast<const uint2*>(&sF[hiR * FSP + kb]);
                #pragma unroll
                for (int nt = 0; nt < 2; nt++) {
                    uint2 b = *reinterpret_cast<const uint2*>(
                        &Wt[(nbase + nt * 8 + r0) * FSP + kb]);
                    mma_tf32(c[nt], alo.x, ahi.x, alo.y, ahi.y, b.x, b.y);
                }
            }

            const int node = sNode[r0];
            if (node >= 0) {
                float* o = out + (size_t)node * 128;
                #pragma unroll
                for (int nt = 0; nt < 2; nt++) {
                    int v0 = nbase + nt * 8 + 2 * c0;
                    if (m == 0) {            // scalar (lo only; hi = pad)
                        o[v0]     = c[nt][0];
                        o[v0 + 1] = c[nt][1];
                    } else if (m == 1) {     // lo = x, hi = y
                        o[32 + 3 * v0 + 0]       = c[nt][0];
                        o[32 + 3 * (v0 + 1) + 0] = c[nt][1];
                        o[32 + 3 * v0 + 1]       = c[nt][2];
                        o[32 + 3 * (v0 + 1) + 1] = c[nt][3];
                    } else {                 // lo = z (hi = pad)
                        o[32 + 3 * v0 + 2]       = c[nt][0];
                        o[32 + 3 * (v0 + 1) + 2] = c[nt][1];
                    }
                }
            }
        }
    }
}

// ---------------------------------------------------------------------------
extern "C" void kernel_launch(void* const* d_in, const int* in_sizes, int n_in,
                              void* d_out, int out_size)
{
    const float* nf       = (const float*)d_in[0];
    const float* sh       = (const float*)d_in[1];
    const int*   senders  = (const int*)  d_in[2];
    const int*   recv     = (const int*)  d_in[3];
    const float* W0       = (const float*)d_in[4];
    const float* W1       = (const float*)d_in[5];
    const float* Ws0      = (const float*)d_in[6];
    const float* Ws1      = (const float*)d_in[7];
    float* out = (float*)d_out;

    int N = in_sizes[0] / 128;
    int E = in_sizes[2];
    int nb = (N + 255) / 256;

    k_fill <<<(E + 511) / 512, 512>>>(recv, senders, E);
    k_count<<<nb, 256>>>(N);
    k_scan <<<1, 64>>>(nb);
    k_place<<<nb, 256>>>(N);
    k_main <<<NBLK, 256>>>(nf, sh, W0, W1, Ws0, Ws1, out, N);
}